// round 2
// baseline (speedup 1.0000x reference)
#include <cuda_runtime.h>

// Dense image warp (tfa.image.dense_image_warp), fp32.
// image: [B,H,W,C], flow: [B,H,W,2] (dy,dx). query = grid - flow.
// y0 = clip(floor(qy), 0, H-2); alpha = clip(q - y0, 0, 1); bilinear.

constexpr int B = 8;
constexpr int H = 1024;
constexpr int W = 768;
constexpr int C = 3;
constexpr int NPIX = B * H * W;

__global__ __launch_bounds__(256) void warp_kernel(
    const float* __restrict__ img,
    const float2* __restrict__ flow,
    float* __restrict__ out)
{
    int idx = blockIdx.x * blockDim.x + threadIdx.x;
    if (idx >= NPIX) return;

    int x = idx % W;
    int t = idx / W;
    int y = t % H;
    int b = t / H;

    float2 f = flow[idx];           // f.x = dy, f.y = dx
    float qy = (float)y - f.x;
    float qx = (float)x - f.y;

    float y0f = fminf(fmaxf(floorf(qy), 0.0f), (float)(H - 2));
    float x0f = fminf(fmaxf(floorf(qx), 0.0f), (float)(W - 2));
    float ay  = fminf(fmaxf(qy - y0f, 0.0f), 1.0f);
    float ax  = fminf(fmaxf(qx - x0f, 0.0f), 1.0f);

    int y0 = (int)y0f;
    int x0 = (int)x0f;

    const float* p = img + ((size_t)((b * H + y0) * W + x0)) * C; // top-left tap
    const float* q = p + (size_t)W * C;                           // bottom-left tap

    float o0, o1, o2;
    {
        // top row: 6 consecutive floats (tl[0..2], tr[0..2]); bottom likewise
        float tl0 = __ldg(p + 0), tl1 = __ldg(p + 1), tl2 = __ldg(p + 2);
        float tr0 = __ldg(p + 3), tr1 = __ldg(p + 4), tr2 = __ldg(p + 5);
        float bl0 = __ldg(q + 0), bl1 = __ldg(q + 1), bl2 = __ldg(q + 2);
        float br0 = __ldg(q + 3), br1 = __ldg(q + 4), br2 = __ldg(q + 5);

        float top0 = fmaf(ax, tr0 - tl0, tl0);
        float top1 = fmaf(ax, tr1 - tl1, tl1);
        float top2 = fmaf(ax, tr2 - tl2, tl2);
        float bot0 = fmaf(ax, br0 - bl0, bl0);
        float bot1 = fmaf(ax, br1 - bl1, bl1);
        float bot2 = fmaf(ax, br2 - bl2, bl2);

        o0 = fmaf(ay, bot0 - top0, top0);
        o1 = fmaf(ay, bot1 - top1, top1);
        o2 = fmaf(ay, bot2 - top2, top2);
    }

    float* op = out + (size_t)idx * 3;
    op[0] = o0;
    op[1] = o1;
    op[2] = o2;
}

extern "C" void kernel_launch(void* const* d_in, const int* in_sizes, int n_in,
                              void* d_out, int out_size)
{
    const float*  img  = (const float*)d_in[0];
    const float2* flow = (const float2*)d_in[1];
    float*        out  = (float*)d_out;

    int threads = 256;
    int blocks  = (NPIX + threads - 1) / threads;
    warp_kernel<<<blocks, threads>>>(img, flow, out);
}

// round 7
// speedup vs baseline: 1.1538x; 1.1538x over previous
#include <cuda_runtime.h>

// Dense image warp (tfa.image.dense_image_warp), fp32.
// image: [B,H,W,C], flow: [B,H,W,2] (dy,dx). query = grid - flow.
//
// R2 candidate, resubmit #3 (R3/R5 were GB300 broker failures, no data):
//  - 4 pixels/thread (same row; W%4==0 so no row crossing).
//  - flow: 2x LDG.128, output: 3x STG.128.
//  - taps: each row's 6 consecutive floats via aligned 32B window
//    [pix3 & ~3, +8 floats) as 2x LDG.128 + predicated scalar tail (off==3),
//    routed with selects. Top/bottom rows share `off` (row stride 2304
//    floats is a multiple of 4).

constexpr int B = 8;
constexpr int H = 1024;
constexpr int W = 768;
constexpr int NPIX = B * H * W;           // 6291456, divisible by 4
constexpr int ROW3 = W * 3;               // 2304 floats, multiple of 4

__device__ __forceinline__ float sel4(bool o1, bool o2,
                                      float v0, float v1, float v2, float v3)
{
    float lo = o1 ? v1 : v0;
    float hi = o1 ? v3 : v2;
    return o2 ? hi : lo;
}

__global__ __launch_bounds__(256, 2) void warp_kernel(
    const float*  __restrict__ img,
    const float4* __restrict__ flow4,
    float4*       __restrict__ out4)
{
    int t = blockIdx.x * blockDim.x + threadIdx.x;   // one thread = 4 pixels
    int idx0 = t * 4;

    int xb  = idx0 % W;        // base x of the 4-pixel group
    int row = idx0 / W;
    int y   = row % H;
    int b   = row / H;

    float4 fA = __ldg(flow4 + 2 * t);
    float4 fB = __ldg(flow4 + 2 * t + 1);
    float dys[4] = {fA.x, fA.z, fB.x, fB.z};
    float dxs[4] = {fA.y, fA.w, fB.y, fB.w};

    float res[12];
    const float fy = (float)y;
    const int bh = b * H;

#pragma unroll
    for (int i = 0; i < 4; i++) {
        float qy = fy - dys[i];
        float qx = (float)(xb + i) - dxs[i];

        float y0f = fminf(fmaxf(floorf(qy), 0.0f), (float)(H - 2));
        float x0f = fminf(fmaxf(floorf(qx), 0.0f), (float)(W - 2));
        float ay  = fminf(fmaxf(qy - y0f, 0.0f), 1.0f);
        float ax  = fminf(fmaxf(qx - x0f, 0.0f), 1.0f);

        int y0 = (int)y0f;
        int x0 = (int)x0f;

        int pix3 = ((bh + y0) * W + x0) * 3;   // float index of tl[0]
        int a    = pix3 & ~3;                  // 16B-aligned window base
        int off  = pix3 & 3;
        bool o1 = (off & 1) != 0;
        bool o2 = (off & 2) != 0;
        bool o3 = (off == 3);

        const float4* pt = (const float4*)(img + a);
        const float4* pb = (const float4*)(img + a + ROW3);
        float4 t0 = __ldg(pt);
        float4 t1 = __ldg(pt + 1);
        float4 b0 = __ldg(pb);
        float4 b1 = __ldg(pb + 1);
        float tt = o3 ? __ldg(img + a + 8)        : 0.0f;  // predicated tail
        float bb = o3 ? __ldg(img + a + ROW3 + 8) : 0.0f;

        // route window -> taps (w_j = window[off + j])
        float tl0 = sel4(o1, o2, t0.x, t0.y, t0.z, t0.w);
        float tl1 = sel4(o1, o2, t0.y, t0.z, t0.w, t1.x);
        float tl2 = sel4(o1, o2, t0.z, t0.w, t1.x, t1.y);
        float tr0 = sel4(o1, o2, t0.w, t1.x, t1.y, t1.z);
        float tr1 = sel4(o1, o2, t1.x, t1.y, t1.z, t1.w);
        float tr2 = sel4(o1, o2, t1.y, t1.z, t1.w, tt);

        float bl0 = sel4(o1, o2, b0.x, b0.y, b0.z, b0.w);
        float bl1 = sel4(o1, o2, b0.y, b0.z, b0.w, b1.x);
        float bl2 = sel4(o1, o2, b0.z, b0.w, b1.x, b1.y);
        float br0 = sel4(o1, o2, b0.w, b1.x, b1.y, b1.z);
        float br1 = sel4(o1, o2, b1.x, b1.y, b1.z, b1.w);
        float br2 = sel4(o1, o2, b1.y, b1.z, b1.w, bb);

        float top0 = fmaf(ax, tr0 - tl0, tl0);
        float top1 = fmaf(ax, tr1 - tl1, tl1);
        float top2 = fmaf(ax, tr2 - tl2, tl2);
        float bot0 = fmaf(ax, br0 - bl0, bl0);
        float bot1 = fmaf(ax, br1 - bl1, bl1);
        float bot2 = fmaf(ax, br2 - bl2, bl2);

        res[i * 3 + 0] = fmaf(ay, bot0 - top0, top0);
        res[i * 3 + 1] = fmaf(ay, bot1 - top1, top1);
        res[i * 3 + 2] = fmaf(ay, bot2 - top2, top2);
    }

    float4* o = out4 + 3 * t;
    o[0] = make_float4(res[0], res[1],  res[2],  res[3]);
    o[1] = make_float4(res[4], res[5],  res[6],  res[7]);
    o[2] = make_float4(res[8], res[9],  res[10], res[11]);
}

extern "C" void kernel_launch(void* const* d_in, const int* in_sizes, int n_in,
                              void* d_out, int out_size)
{
    const float*  img  = (const float*)d_in[0];
    const float4* flow = (const float4*)d_in[1];
    float4*       out  = (float4*)d_out;

    int nthreads = NPIX / 4;           // 1572864
    int threads  = 256;
    int blocks   = nthreads / threads; // 6144, exact
    warp_kernel<<<blocks, threads>>>(img, flow, out);
}

// round 10
// speedup vs baseline: 1.2751x; 1.1051x over previous
#include <cuda_runtime.h>

// Dense image warp (tfa.image.dense_image_warp), fp32.
// image: [B,H,W,C], flow: [B,H,W,2] (dy,dx). query = grid - flow.
//
// R7: same access structure as R6 winner (4 px/thread, window-vectorized taps,
// vector flow/output), but __launch_bounds__(256,3) to lift occupancy
// 20% -> ~36% (R6 measured regs=104 -> occ-capped, latency-exposed).

constexpr int B = 8;
constexpr int H = 1024;
constexpr int W = 768;
constexpr int NPIX = B * H * W;           // 6291456, divisible by 4
constexpr int ROW3 = W * 3;               // 2304 floats, multiple of 4

__device__ __forceinline__ float sel4(bool o1, bool o2,
                                      float v0, float v1, float v2, float v3)
{
    float lo = o1 ? v1 : v0;
    float hi = o1 ? v3 : v2;
    return o2 ? hi : lo;
}

__global__ __launch_bounds__(256, 3) void warp_kernel(
    const float*  __restrict__ img,
    const float4* __restrict__ flow4,
    float4*       __restrict__ out4)
{
    int t = blockIdx.x * blockDim.x + threadIdx.x;   // one thread = 4 pixels
    int idx0 = t * 4;

    int xb  = idx0 % W;        // base x of the 4-pixel group
    int row = idx0 / W;
    int y   = row % H;
    int b   = row / H;

    float4 fA = __ldg(flow4 + 2 * t);
    float4 fB = __ldg(flow4 + 2 * t + 1);
    float dys[4] = {fA.x, fA.z, fB.x, fB.z};
    float dxs[4] = {fA.y, fA.w, fB.y, fB.w};

    float res[12];
    const float fy = (float)y;
    const int bh = b * H;

#pragma unroll
    for (int i = 0; i < 4; i++) {
        float qy = fy - dys[i];
        float qx = (float)(xb + i) - dxs[i];

        float y0f = fminf(fmaxf(floorf(qy), 0.0f), (float)(H - 2));
        float x0f = fminf(fmaxf(floorf(qx), 0.0f), (float)(W - 2));
        float ay  = fminf(fmaxf(qy - y0f, 0.0f), 1.0f);
        float ax  = fminf(fmaxf(qx - x0f, 0.0f), 1.0f);

        int y0 = (int)y0f;
        int x0 = (int)x0f;

        int pix3 = ((bh + y0) * W + x0) * 3;   // float index of tl[0]
        int a    = pix3 & ~3;                  // 16B-aligned window base
        int off  = pix3 & 3;
        bool o1 = (off & 1) != 0;
        bool o2 = (off & 2) != 0;
        bool o3 = (off == 3);

        const float4* pt = (const float4*)(img + a);
        const float4* pb = (const float4*)(img + a + ROW3);
        float4 t0 = __ldg(pt);
        float4 t1 = __ldg(pt + 1);
        float4 b0 = __ldg(pb);
        float4 b1 = __ldg(pb + 1);
        float tt = o3 ? __ldg(img + a + 8)        : 0.0f;  // predicated tail
        float bb = o3 ? __ldg(img + a + ROW3 + 8) : 0.0f;

        // route window -> taps (w_j = window[off + j])
        float tl0 = sel4(o1, o2, t0.x, t0.y, t0.z, t0.w);
        float tl1 = sel4(o1, o2, t0.y, t0.z, t0.w, t1.x);
        float tl2 = sel4(o1, o2, t0.z, t0.w, t1.x, t1.y);
        float tr0 = sel4(o1, o2, t0.w, t1.x, t1.y, t1.z);
        float tr1 = sel4(o1, o2, t1.x, t1.y, t1.z, t1.w);
        float tr2 = sel4(o1, o2, t1.y, t1.z, t1.w, tt);

        float bl0 = sel4(o1, o2, b0.x, b0.y, b0.z, b0.w);
        float bl1 = sel4(o1, o2, b0.y, b0.z, b0.w, b1.x);
        float bl2 = sel4(o1, o2, b0.z, b0.w, b1.x, b1.y);
        float br0 = sel4(o1, o2, b0.w, b1.x, b1.y, b1.z);
        float br1 = sel4(o1, o2, b1.x, b1.y, b1.z, b1.w);
        float br2 = sel4(o1, o2, b1.y, b1.z, b1.w, bb);

        float top0 = fmaf(ax, tr0 - tl0, tl0);
        float top1 = fmaf(ax, tr1 - tl1, tl1);
        float top2 = fmaf(ax, tr2 - tl2, tl2);
        float bot0 = fmaf(ax, br0 - bl0, bl0);
        float bot1 = fmaf(ax, br1 - bl1, bl1);
        float bot2 = fmaf(ax, br2 - bl2, bl2);

        res[i * 3 + 0] = fmaf(ay, bot0 - top0, top0);
        res[i * 3 + 1] = fmaf(ay, bot1 - top1, top1);
        res[i * 3 + 2] = fmaf(ay, bot2 - top2, top2);
    }

    float4* o = out4 + 3 * t;
    o[0] = make_float4(res[0], res[1],  res[2],  res[3]);
    o[1] = make_float4(res[4], res[5],  res[6],  res[7]);
    o[2] = make_float4(res[8], res[9],  res[10], res[11]);
}

extern "C" void kernel_launch(void* const* d_in, const int* in_sizes, int n_in,
                              void* d_out, int out_size)
{
    const float*  img  = (const float*)d_in[0];
    const float4* flow = (const float4*)d_in[1];
    float4*       out  = (float4*)d_out;

    int nthreads = NPIX / 4;           // 1572864
    int threads  = 256;
    int blocks   = nthreads / threads; // 6144, exact
    warp_kernel<<<blocks, threads>>>(img, flow, out);
}